// round 2
// baseline (speedup 1.0000x reference)
#include <cuda_runtime.h>
#include <math.h>

// Problem constants
#define BB 4
#define NN 1024
#define DD 1024
#define HH 16
#define DHH 64
#define INNERC 1024          // HH*DHH
#define QKVC 3072            // 3*INNERC
#define MM 4096              // BB*NN
#define BHC 64               // BB*HH

// Scratch (allocation-free rule: __device__ globals)
__device__ float g_qkv[(size_t)MM * QKVC];       // [B*N, 3*INNER]
__device__ float g_S[(size_t)BHC * NN * NN];     // [B*H, N, N] scores -> probs (in place)
__device__ float g_ao[(size_t)MM * INNERC];      // [B*N, INNER] attention output

// ---------------------------------------------------------------------------
// Generic fp32 SGEMM: C[M,Nc] = A[M,K] @ B[K,Nc] (+bias), all row-major dense.
// 128x128 tile, BK=16, 256 threads, 8x8 micro-tile per thread.
// Grid: (Nc/128, M/128). Requires M%128==0, Nc%128==0, K%16==0.
// ---------------------------------------------------------------------------
__global__ void __launch_bounds__(256) sgemm128(
    const float* __restrict__ A, const float* __restrict__ Bmat,
    const float* __restrict__ bias, float* __restrict__ C,
    int K, int Nc)
{
    __shared__ float As[16][128];
    __shared__ float Bs[16][128];
    const int tid = threadIdx.x;
    const int tx = tid & 15;
    const int ty = tid >> 4;
    const int m0 = blockIdx.y * 128;
    const int n0 = blockIdx.x * 128;

    const int arow = tid >> 2;         // 0..63
    const int ak   = (tid & 3) << 2;   // 0,4,8,12
    const int bk   = tid >> 5;         // 0..7
    const int bn   = (tid & 31) << 2;  // 0..124

    float acc[8][8];
#pragma unroll
    for (int i = 0; i < 8; ++i)
#pragma unroll
        for (int j = 0; j < 8; ++j) acc[i][j] = 0.f;

    for (int k0 = 0; k0 < K; k0 += 16) {
        float4 a0 = *(const float4*)(A + (size_t)(m0 + arow) * K + k0 + ak);
        float4 a1 = *(const float4*)(A + (size_t)(m0 + arow + 64) * K + k0 + ak);
        As[ak + 0][arow] = a0.x; As[ak + 1][arow] = a0.y;
        As[ak + 2][arow] = a0.z; As[ak + 3][arow] = a0.w;
        As[ak + 0][arow + 64] = a1.x; As[ak + 1][arow + 64] = a1.y;
        As[ak + 2][arow + 64] = a1.z; As[ak + 3][arow + 64] = a1.w;

        float4 b0 = *(const float4*)(Bmat + (size_t)(k0 + bk) * Nc + n0 + bn);
        float4 b1 = *(const float4*)(Bmat + (size_t)(k0 + bk + 8) * Nc + n0 + bn);
        *(float4*)(&Bs[bk][bn])     = b0;
        *(float4*)(&Bs[bk + 8][bn]) = b1;
        __syncthreads();

#pragma unroll
        for (int kk = 0; kk < 16; ++kk) {
            float a[8], b[8];
            *(float4*)(a)     = *(const float4*)(&As[kk][ty * 8]);
            *(float4*)(a + 4) = *(const float4*)(&As[kk][ty * 8 + 4]);
            *(float4*)(b)     = *(const float4*)(&Bs[kk][tx * 8]);
            *(float4*)(b + 4) = *(const float4*)(&Bs[kk][tx * 8 + 4]);
#pragma unroll
            for (int i = 0; i < 8; ++i)
#pragma unroll
                for (int j = 0; j < 8; ++j)
                    acc[i][j] += a[i] * b[j];
        }
        __syncthreads();
    }

#pragma unroll
    for (int i = 0; i < 8; ++i) {
        const int m = m0 + ty * 8 + i;
#pragma unroll
        for (int j = 0; j < 8; j += 4) {
            const int n = n0 + tx * 8 + j;
            float4 v = make_float4(acc[i][j], acc[i][j + 1], acc[i][j + 2], acc[i][j + 3]);
            if (bias) {
                v.x += bias[n]; v.y += bias[n + 1]; v.z += bias[n + 2]; v.w += bias[n + 3];
            }
            *(float4*)(C + (size_t)m * Nc + n) = v;
        }
    }
}

// ---------------------------------------------------------------------------
// S[bh, i, j] = (1/8) * sum_d q[b,h,i,d] * k[b,h,j,d]
// q,k live inside g_qkv: q[b,n, h*64+d], k at +INNER offset. Both K-major (NT GEMM).
// 128x128 tile over (i, j), K=DH=64 in BK=16 chunks.
// Grid: (N/128, N/128, BH)
// ---------------------------------------------------------------------------
__global__ void __launch_bounds__(256) qk_scores(
    const float* __restrict__ qkv, float* __restrict__ S)
{
    __shared__ float Qs[16][128];
    __shared__ float Ks[16][128];
    const int tid = threadIdx.x;
    const int tx = tid & 15;
    const int ty = tid >> 4;
    const int bh = blockIdx.z;
    const int b = bh >> 4;
    const int h = bh & 15;
    const float* qbase = qkv + (size_t)b * NN * QKVC + h * DHH;
    const float* kbase = qbase + INNERC;
    const int i0 = blockIdx.y * 128;
    const int j0 = blockIdx.x * 128;
    const int arow = tid >> 2;
    const int ak = (tid & 3) << 2;

    float acc[8][8];
#pragma unroll
    for (int i = 0; i < 8; ++i)
#pragma unroll
        for (int j = 0; j < 8; ++j) acc[i][j] = 0.f;

    for (int k0 = 0; k0 < DHH; k0 += 16) {
        float4 q0 = *(const float4*)(qbase + (size_t)(i0 + arow) * QKVC + k0 + ak);
        float4 q1 = *(const float4*)(qbase + (size_t)(i0 + arow + 64) * QKVC + k0 + ak);
        Qs[ak + 0][arow] = q0.x; Qs[ak + 1][arow] = q0.y;
        Qs[ak + 2][arow] = q0.z; Qs[ak + 3][arow] = q0.w;
        Qs[ak + 0][arow + 64] = q1.x; Qs[ak + 1][arow + 64] = q1.y;
        Qs[ak + 2][arow + 64] = q1.z; Qs[ak + 3][arow + 64] = q1.w;

        float4 kv0 = *(const float4*)(kbase + (size_t)(j0 + arow) * QKVC + k0 + ak);
        float4 kv1 = *(const float4*)(kbase + (size_t)(j0 + arow + 64) * QKVC + k0 + ak);
        Ks[ak + 0][arow] = kv0.x; Ks[ak + 1][arow] = kv0.y;
        Ks[ak + 2][arow] = kv0.z; Ks[ak + 3][arow] = kv0.w;
        Ks[ak + 0][arow + 64] = kv1.x; Ks[ak + 1][arow + 64] = kv1.y;
        Ks[ak + 2][arow + 64] = kv1.z; Ks[ak + 3][arow + 64] = kv1.w;
        __syncthreads();

#pragma unroll
        for (int kk = 0; kk < 16; ++kk) {
            float a[8], b[8];
            *(float4*)(a)     = *(const float4*)(&Qs[kk][ty * 8]);
            *(float4*)(a + 4) = *(const float4*)(&Qs[kk][ty * 8 + 4]);
            *(float4*)(b)     = *(const float4*)(&Ks[kk][tx * 8]);
            *(float4*)(b + 4) = *(const float4*)(&Ks[kk][tx * 8 + 4]);
#pragma unroll
            for (int i = 0; i < 8; ++i)
#pragma unroll
                for (int j = 0; j < 8; ++j)
                    acc[i][j] += a[i] * b[j];
        }
        __syncthreads();
    }

    const float scale = 0.125f;  // DH^-0.5 = 1/8 exactly
    float* srow = S + (size_t)bh * NN * NN;
#pragma unroll
    for (int i = 0; i < 8; ++i) {
        const int m = i0 + ty * 8 + i;
#pragma unroll
        for (int j = 0; j < 8; j += 4) {
            const int n = j0 + tx * 8 + j;
            float4 v = make_float4(acc[i][j] * scale, acc[i][j + 1] * scale,
                                   acc[i][j + 2] * scale, acc[i][j + 3] * scale);
            *(float4*)(srow + (size_t)m * NN + n) = v;
        }
    }
}

// ---------------------------------------------------------------------------
// Masked softmax, in place over each row of S.
// blocked(i,j) iff mask[b,i]*mask[b,j] == 0. Fully-blocked rows -> exact zeros.
// One block (256 thr) per row; each thread owns 4 contiguous columns.
// Grid: BH*N blocks.
// ---------------------------------------------------------------------------
__global__ void __launch_bounds__(256) softmax_rows(
    float* __restrict__ S, const float* __restrict__ mask)
{
    const int r = blockIdx.x;          // bh*N + i
    const int i = r & (NN - 1);
    const int bh = r >> 10;
    const int b = bh >> 4;
    float* row = S + (size_t)r * NN;
    const float* mrow = mask + b * NN;
    const int tid = threadIdx.x;
    __shared__ float red[256];

    const float mi = mrow[i];
    const int j = tid << 2;
    const float4 rv = *(const float4*)(row + j);
    const float4 mv = *(const float4*)(mrow + j);

    float mx = -INFINITY;
    if (mv.x != 0.f) mx = fmaxf(mx, rv.x);
    if (mv.y != 0.f) mx = fmaxf(mx, rv.y);
    if (mv.z != 0.f) mx = fmaxf(mx, rv.z);
    if (mv.w != 0.f) mx = fmaxf(mx, rv.w);
    red[tid] = mx;
    __syncthreads();
#pragma unroll
    for (int s = 128; s > 0; s >>= 1) {
        if (tid < s) red[tid] = fmaxf(red[tid], red[tid + s]);
        __syncthreads();
    }
    mx = red[0];
    __syncthreads();

    float4 e;
    e.x = (mv.x != 0.f) ? __expf(rv.x - mx) : 0.f;
    e.y = (mv.y != 0.f) ? __expf(rv.y - mx) : 0.f;
    e.z = (mv.z != 0.f) ? __expf(rv.z - mx) : 0.f;
    e.w = (mv.w != 0.f) ? __expf(rv.w - mx) : 0.f;

    red[tid] = e.x + e.y + e.z + e.w;
    __syncthreads();
#pragma unroll
    for (int s = 128; s > 0; s >>= 1) {
        if (tid < s) red[tid] += red[tid + s];
        __syncthreads();
    }
    const float sum = red[0];

    const bool validrow = (mi != 0.f) && (mx != -INFINITY);
    const float inv = validrow ? 1.f / sum : 0.f;
    e.x *= inv; e.y *= inv; e.z *= inv; e.w *= inv;
    *(float4*)(row + j) = e;
}

// ---------------------------------------------------------------------------
// ao[b, i, h*64+d] = sum_j P[bh,i,j] * v[b,j,h,d]
// 128x64 tile (full DH per block), K=N=1024 in BK=16 chunks.
// Grid: (N/128, BH)
// ---------------------------------------------------------------------------
__global__ void __launch_bounds__(256) pv_gemm(
    const float* __restrict__ S, const float* __restrict__ qkv,
    float* __restrict__ ao)
{
    __shared__ float Ps[16][128];
    __shared__ float Vs[16][64];
    const int tid = threadIdx.x;
    const int tx = tid & 15;           // col group: n = tx*4
    const int ty = tid >> 4;           // row group: m = ty*8
    const int bh = blockIdx.y;
    const int b = bh >> 4;
    const int h = bh & 15;
    const int i0 = blockIdx.x * 128;
    const float* pbase = S + (size_t)bh * NN * NN;
    const float* vbase = qkv + (size_t)b * NN * QKVC + 2 * INNERC + h * DHH;
    float* obase = ao + (size_t)b * NN * INNERC + h * DHH;

    const int arow = tid >> 2;         // 0..63
    const int ak = (tid & 3) << 2;
    const int vk = tid >> 4;           // 0..15
    const int vn = (tid & 15) << 2;    // 0..60

    float acc[8][4];
#pragma unroll
    for (int i = 0; i < 8; ++i)
#pragma unroll
        for (int j = 0; j < 4; ++j) acc[i][j] = 0.f;

    for (int j0 = 0; j0 < NN; j0 += 16) {
        float4 p0 = *(const float4*)(pbase + (size_t)(i0 + arow) * NN + j0 + ak);
        float4 p1 = *(const float4*)(pbase + (size_t)(i0 + arow + 64) * NN + j0 + ak);
        Ps[ak + 0][arow] = p0.x; Ps[ak + 1][arow] = p0.y;
        Ps[ak + 2][arow] = p0.z; Ps[ak + 3][arow] = p0.w;
        Ps[ak + 0][arow + 64] = p1.x; Ps[ak + 1][arow + 64] = p1.y;
        Ps[ak + 2][arow + 64] = p1.z; Ps[ak + 3][arow + 64] = p1.w;

        float4 v0 = *(const float4*)(vbase + (size_t)(j0 + vk) * QKVC + vn);
        *(float4*)(&Vs[vk][vn]) = v0;
        __syncthreads();

#pragma unroll
        for (int kk = 0; kk < 16; ++kk) {
            float a[8], bb[4];
            *(float4*)(a)     = *(const float4*)(&Ps[kk][ty * 8]);
            *(float4*)(a + 4) = *(const float4*)(&Ps[kk][ty * 8 + 4]);
            *(float4*)(bb)    = *(const float4*)(&Vs[kk][tx * 4]);
#pragma unroll
            for (int i = 0; i < 8; ++i)
#pragma unroll
                for (int j = 0; j < 4; ++j)
                    acc[i][j] += a[i] * bb[j];
        }
        __syncthreads();
    }

#pragma unroll
    for (int i = 0; i < 8; ++i) {
        const int m = i0 + ty * 8 + i;
        float4 v = make_float4(acc[i][0], acc[i][1], acc[i][2], acc[i][3]);
        *(float4*)(obase + (size_t)m * INNERC + tx * 4) = v;
    }
}

// ---------------------------------------------------------------------------
extern "C" void kernel_launch(void* const* d_in, const int* in_sizes, int n_in,
                              void* d_out, int out_size)
{
    const float* x      = (const float*)d_in[0];
    const float* mask   = (const float*)d_in[1];
    const float* w_qkv  = (const float*)d_in[2];
    const float* w_out  = (const float*)d_in[3];
    const float* b_out  = (const float*)d_in[4];
    float* out = (float*)d_out;

    float *qkv, *S, *ao;
    cudaGetSymbolAddress((void**)&qkv, g_qkv);
    cudaGetSymbolAddress((void**)&S, g_S);
    cudaGetSymbolAddress((void**)&ao, g_ao);

    // 1) qkv = x @ w_qkv                       [4096,1024]@[1024,3072]
    sgemm128<<<dim3(QKVC / 128, MM / 128), 256>>>(x, w_qkv, nullptr, qkv, DD, QKVC);
    // 2) S = (1/8) q k^T per head              64 x [1024,64]@[64,1024]
    qk_scores<<<dim3(NN / 128, NN / 128, BHC), 256>>>(qkv, S);
    // 3) masked softmax in place
    softmax_rows<<<BHC * NN, 256>>>(S, mask);
    // 4) ao = P @ V per head                   64 x [1024,1024]@[1024,64]
    pv_gemm<<<dim3(NN / 128, BHC), 256>>>(S, qkv, ao);
    // 5) out = ao @ w_out + b_out              [4096,1024]@[1024,1024]
    sgemm128<<<dim3(INNERC / 128, MM / 128), 256>>>(ao, w_out, b_out, out, INNERC, INNERC);
}

// round 5
// speedup vs baseline: 1.3893x; 1.3893x over previous
#include <cuda_runtime.h>
#include <cuda_bf16.h>
#include <math.h>
#include <cstdint>

// Problem constants
#define BB 4
#define NN 1024
#define DD 1024
#define HH 16
#define DHH 64
#define INNERC 1024          // HH*DHH
#define QKVC 3072            // 3*INNERC
#define MM 4096              // BB*NN
#define BHC 64               // BB*HH

// ---------------------------------------------------------------------------
// Scratch (allocation-free rule: __device__ globals)
// ---------------------------------------------------------------------------
__device__ float g_qkv[(size_t)MM * QKVC];       // [B*N, 3*INNER]
__device__ float g_S[(size_t)BHC * NN * NN];     // [B*H, N, N] scores -> probs
__device__ float g_ao[(size_t)MM * INNERC];      // [B*N, INNER]

// bf16 hi/lo splits for tensor-core GEMMs
__device__ __nv_bfloat16 g_xhi[(size_t)MM * DD];
__device__ __nv_bfloat16 g_xlo[(size_t)MM * DD];
__device__ __nv_bfloat16 g_wqkvThi[(size_t)QKVC * DD];   // [3I, D] = w_qkv^T
__device__ __nv_bfloat16 g_wqkvTlo[(size_t)QKVC * DD];
__device__ __nv_bfloat16 g_woutThi[(size_t)INNERC * INNERC];
__device__ __nv_bfloat16 g_woutTlo[(size_t)INNERC * INNERC];
__device__ __nv_bfloat16 g_aohi[(size_t)MM * INNERC];
__device__ __nv_bfloat16 g_aolo[(size_t)MM * INNERC];

// ---------------------------------------------------------------------------
// PTX helpers — sm_80-compatible (compile on plain compute_103 target)
// ---------------------------------------------------------------------------
__device__ __forceinline__ uint32_t smem_u32(const void* p) {
    uint32_t a;
    asm("{ .reg .u64 t; cvta.to.shared.u64 t, %1; cvt.u32.u64 %0, t; }"
        : "=r"(a) : "l"(p));
    return a;
}
#define LDSM4(r, addr) \
    asm volatile("ldmatrix.sync.aligned.m8n8.x4.shared.b16 {%0,%1,%2,%3}, [%4];" \
        : "=r"((r)[0]), "=r"((r)[1]), "=r"((r)[2]), "=r"((r)[3]) : "r"(addr))
#define MMA_BF16(d, a, b) \
    asm volatile("mma.sync.aligned.m16n8k16.row.col.f32.bf16.bf16.f32 " \
        "{%0,%1,%2,%3}, {%4,%5,%6,%7}, {%8,%9}, {%0,%1,%2,%3};" \
        : "+f"((d)[0]), "+f"((d)[1]), "+f"((d)[2]), "+f"((d)[3]) \
        : "r"((a)[0]), "r"((a)[1]), "r"((a)[2]), "r"((a)[3]), \
          "r"((b)[0]), "r"((b)[1]))
#define CP16(saddr, g) \
    asm volatile("cp.async.cg.shared.global [%0], [%1], 16;" :: "r"(saddr), "l"(g))
#define CP_COMMIT() asm volatile("cp.async.commit_group;" ::: "memory")
#define CP_WAIT0()  asm volatile("cp.async.wait_group 0;" ::: "memory")

// ---------------------------------------------------------------------------
// split: fp32 -> (hi, lo) bf16, same layout.
// ---------------------------------------------------------------------------
__global__ void __launch_bounds__(256) split_kernel(
    const float* __restrict__ in, __nv_bfloat16* __restrict__ hi,
    __nv_bfloat16* __restrict__ lo, int n4)
{
    int i = blockIdx.x * 256 + threadIdx.x;
    if (i >= n4) return;
    float4 v = *(const float4*)(in + i * 4);
    __nv_bfloat16 h0 = __float2bfloat16(v.x);
    __nv_bfloat16 h1 = __float2bfloat16(v.y);
    __nv_bfloat16 h2 = __float2bfloat16(v.z);
    __nv_bfloat16 h3 = __float2bfloat16(v.w);
    __nv_bfloat162 hp0 = __nv_bfloat162(h0, h1);
    __nv_bfloat162 hp1 = __nv_bfloat162(h2, h3);
    __nv_bfloat162 lp0 = __nv_bfloat162(__float2bfloat16(v.x - __bfloat162float(h0)),
                                        __float2bfloat16(v.y - __bfloat162float(h1)));
    __nv_bfloat162 lp1 = __nv_bfloat162(__float2bfloat16(v.z - __bfloat162float(h2)),
                                        __float2bfloat16(v.w - __bfloat162float(h3)));
    *(__nv_bfloat162*)(hi + i * 4) = hp0;
    *(__nv_bfloat162*)(hi + i * 4 + 2) = hp1;
    *(__nv_bfloat162*)(lo + i * 4) = lp0;
    *(__nv_bfloat162*)(lo + i * 4 + 2) = lp1;
}

// ---------------------------------------------------------------------------
// splitT: fp32 [R,C] -> transposed (hi, lo) bf16 [C,R].
// ---------------------------------------------------------------------------
__global__ void __launch_bounds__(256) splitT_kernel(
    const float* __restrict__ in, __nv_bfloat16* __restrict__ hiT,
    __nv_bfloat16* __restrict__ loT, int R, int C)
{
    __shared__ float t[32][33];
    const int c = blockIdx.x * 32 + threadIdx.x;
#pragma unroll
    for (int j = 0; j < 4; ++j) {
        int r = blockIdx.y * 32 + threadIdx.y + j * 8;
        t[threadIdx.y + j * 8][threadIdx.x] = in[(size_t)r * C + c];
    }
    __syncthreads();
    const int rr = blockIdx.y * 32 + threadIdx.x;
#pragma unroll
    for (int j = 0; j < 4; ++j) {
        int cc = blockIdx.x * 32 + threadIdx.y + j * 8;
        float v = t[threadIdx.x][threadIdx.y + j * 8];
        __nv_bfloat16 h = __float2bfloat16(v);
        hiT[(size_t)cc * R + rr] = h;
        loT[(size_t)cc * R + rr] = __float2bfloat16(v - __bfloat162float(h));
    }
}

// ---------------------------------------------------------------------------
// mma.sync bf16 GEMM: C[M,Ncols] = A[M,K] @ Bt[Ncols,K]^T (+bias)
// A,Bt pre-split into bf16 hi/lo; 3-product compensation, fp32 accum.
// 128x128 block tile, BK=32, 8 warps (64x32 warp tile), cp.async double buffer.
// SMEM tiles padded to stride 40 bf16 for conflict-free ldmatrix.
// Grid: (Ncols/128, M/128), 256 threads. K % 32 == 0.
// ---------------------------------------------------------------------------
#define TSTRIDE 40
#define TILE_ELEMS (128 * TSTRIDE)          // 5120 bf16
#define TILEB (TILE_ELEMS * 2)              // 10240 bytes
#define STAGEB (4 * TILEB)                  // 40960 bytes
#define GEMM_SMEM_BYTES (2 * STAGEB)        // 81920 bytes

__global__ void __launch_bounds__(256, 1) gemm_mma(
    const __nv_bfloat16* __restrict__ Ahi, const __nv_bfloat16* __restrict__ Alo,
    const __nv_bfloat16* __restrict__ Bthi, const __nv_bfloat16* __restrict__ Btlo,
    const float* __restrict__ bias, float* __restrict__ C,
    int M, int Ncols, int K)
{
    extern __shared__ char smem[];
    const uint32_t smb = smem_u32(smem);
    const int tid = threadIdx.x;
    const int lane = tid & 31;
    const int wid = tid >> 5;
    const int mw = wid >> 2;            // 0..1
    const int nw = wid & 3;             // 0..3
    const int m0 = blockIdx.y * 128;
    const int n0 = blockIdx.x * 128;

    // ---- global load setup: 2 threads per row, each copies 2x 16B per tile
    const int grow = tid >> 1;                    // 0..127
    const int gcol = (tid & 1) << 4;              // 0 or 16
    const __nv_bfloat16* gAh = Ahi  + (size_t)(m0 + grow) * K + gcol;
    const __nv_bfloat16* gAl = Alo  + (size_t)(m0 + grow) * K + gcol;
    const __nv_bfloat16* gBh = Bthi + (size_t)(n0 + grow) * K + gcol;
    const __nv_bfloat16* gBl = Btlo + (size_t)(n0 + grow) * K + gcol;
    const uint32_t stb = (uint32_t)(grow * TSTRIDE + gcol) * 2;  // byte offset in tile

    // ---- ldmatrix per-thread source offsets (bytes, within a stage)
    uint32_t aoff[4];
#pragma unroll
    for (int mt = 0; mt < 4; ++mt)
        aoff[mt] = (uint32_t)((mw * 64 + mt * 16 + (lane & 15)) * TSTRIDE
                              + ((lane >> 4) << 3)) * 2;
    const int brow = nw * 32 + (lane & 7) + ((lane >> 4) << 3);
    const int bcol = ((lane >> 3) & 1) << 3;
    uint32_t boff[2];
    boff[0] = (uint32_t)(brow * TSTRIDE + bcol) * 2;
    boff[1] = (uint32_t)((brow + 16) * TSTRIDE + bcol) * 2;

    float acc[4][4][4];
#pragma unroll
    for (int i = 0; i < 4; ++i)
#pragma unroll
        for (int j = 0; j < 4; ++j)
#pragma unroll
            for (int k = 0; k < 4; ++k) acc[i][j][k] = 0.f;

    const int nst = K >> 5;   // BK=32

    // prologue: stage 0
    {
        const uint32_t d = smb + stb;
        CP16(d,                 gAh);     CP16(d + 16,                 gAh + 8);
        CP16(d + TILEB,         gAl);     CP16(d + TILEB + 16,         gAl + 8);
        CP16(d + 2 * TILEB,     gBh);     CP16(d + 2 * TILEB + 16,     gBh + 8);
        CP16(d + 3 * TILEB,     gBl);     CP16(d + 3 * TILEB + 16,     gBl + 8);
        CP_COMMIT();
        CP_WAIT0();
    }
    __syncthreads();

    for (int s = 0; s < nst; ++s) {
        // issue next-stage loads (overlap with compute)
        if (s + 1 < nst) {
            const int k0 = (s + 1) << 5;
            const uint32_t d = smb + ((s + 1) & 1) * STAGEB + stb;
            CP16(d,                 gAh + k0);  CP16(d + 16,                 gAh + k0 + 8);
            CP16(d + TILEB,         gAl + k0);  CP16(d + TILEB + 16,         gAl + k0 + 8);
            CP16(d + 2 * TILEB,     gBh + k0);  CP16(d + 2 * TILEB + 16,     gBh + k0 + 8);
            CP16(d + 3 * TILEB,     gBl + k0);  CP16(d + 3 * TILEB + 16,     gBl + k0 + 8);
            CP_COMMIT();
        }

        const uint32_t sb = smb + (s & 1) * STAGEB;
#pragma unroll
        for (int kk = 0; kk < 2; ++kk) {
            const uint32_t kb = kk * 32;     // 16 bf16 = 32 bytes
            uint32_t ah[4][4], al[4][4], bh[4][2], bl[4][2];
#pragma unroll
            for (int mt = 0; mt < 4; ++mt) {
                LDSM4(ah[mt], sb + aoff[mt] + kb);
                LDSM4(al[mt], sb + TILEB + aoff[mt] + kb);
            }
#pragma unroll
            for (int p = 0; p < 2; ++p) {
                uint32_t t4[4];
                LDSM4(t4, sb + 2 * TILEB + boff[p] + kb);
                bh[2 * p][0] = t4[0]; bh[2 * p][1] = t4[1];
                bh[2 * p + 1][0] = t4[2]; bh[2 * p + 1][1] = t4[3];
                LDSM4(t4, sb + 3 * TILEB + boff[p] + kb);
                bl[2 * p][0] = t4[0]; bl[2 * p][1] = t4[1];
                bl[2 * p + 1][0] = t4[2]; bl[2 * p + 1][1] = t4[3];
            }
#pragma unroll
            for (int mt = 0; mt < 4; ++mt)
#pragma unroll
                for (int nt = 0; nt < 4; ++nt) {
                    MMA_BF16(acc[mt][nt], ah[mt], bh[nt]);
                    MMA_BF16(acc[mt][nt], ah[mt], bl[nt]);
                    MMA_BF16(acc[mt][nt], al[mt], bh[nt]);
                }
        }
        CP_WAIT0();
        __syncthreads();
    }

    // ---- epilogue: fragment -> gmem (float2 stores) with optional bias
#pragma unroll
    for (int mt = 0; mt < 4; ++mt) {
        const int r0 = m0 + mw * 64 + mt * 16 + (lane >> 2);
#pragma unroll
        for (int nt = 0; nt < 4; ++nt) {
            const int cc = n0 + nw * 32 + nt * 8 + ((lane & 3) << 1);
            float2 v0 = make_float2(acc[mt][nt][0], acc[mt][nt][1]);
            float2 v1 = make_float2(acc[mt][nt][2], acc[mt][nt][3]);
            if (bias) {
                float2 bv = *(const float2*)(bias + cc);
                v0.x += bv.x; v0.y += bv.y;
                v1.x += bv.x; v1.y += bv.y;
            }
            *(float2*)(C + (size_t)r0 * Ncols + cc) = v0;
            *(float2*)(C + (size_t)(r0 + 8) * Ncols + cc) = v1;
        }
    }
}

// ---------------------------------------------------------------------------
// qk_scores, softmax_rows, pv_gemm — unchanged SIMT (next-round target)
// ---------------------------------------------------------------------------
__global__ void __launch_bounds__(256) qk_scores(
    const float* __restrict__ qkv, float* __restrict__ S)
{
    __shared__ float Qs[16][128];
    __shared__ float Ks[16][128];
    const int tid = threadIdx.x;
    const int tx = tid & 15;
    const int ty = tid >> 4;
    const int bh = blockIdx.z;
    const int b = bh >> 4;
    const int h = bh & 15;
    const float* qbase = qkv + (size_t)b * NN * QKVC + h * DHH;
    const float* kbase = qbase + INNERC;
    const int i0 = blockIdx.y * 128;
    const int j0 = blockIdx.x * 128;
    const int arow = tid >> 2;
    const int ak = (tid & 3) << 2;

    float acc[8][8];
#pragma unroll
    for (int i = 0; i < 8; ++i)
#pragma unroll
        for (int j = 0; j < 8; ++j) acc[i][j] = 0.f;

    for (int k0 = 0; k0 < DHH; k0 += 16) {
        float4 q0 = *(const float4*)(qbase + (size_t)(i0 + arow) * QKVC + k0 + ak);
        float4 q1 = *(const float4*)(qbase + (size_t)(i0 + arow + 64) * QKVC + k0 + ak);
        Qs[ak + 0][arow] = q0.x; Qs[ak + 1][arow] = q0.y;
        Qs[ak + 2][arow] = q0.z; Qs[ak + 3][arow] = q0.w;
        Qs[ak + 0][arow + 64] = q1.x; Qs[ak + 1][arow + 64] = q1.y;
        Qs[ak + 2][arow + 64] = q1.z; Qs[ak + 3][arow + 64] = q1.w;

        float4 kv0 = *(const float4*)(kbase + (size_t)(j0 + arow) * QKVC + k0 + ak);
        float4 kv1 = *(const float4*)(kbase + (size_t)(j0 + arow + 64) * QKVC + k0 + ak);
        Ks[ak + 0][arow] = kv0.x; Ks[ak + 1][arow] = kv0.y;
        Ks[ak + 2][arow] = kv0.z; Ks[ak + 3][arow] = kv0.w;
        Ks[ak + 0][arow + 64] = kv1.x; Ks[ak + 1][arow + 64] = kv1.y;
        Ks[ak + 2][arow + 64] = kv1.z; Ks[ak + 3][arow + 64] = kv1.w;
        __syncthreads();

#pragma unroll
        for (int kk = 0; kk < 16; ++kk) {
            float a[8], b2[8];
            *(float4*)(a)      = *(const float4*)(&Qs[kk][ty * 8]);
            *(float4*)(a + 4)  = *(const float4*)(&Qs[kk][ty * 8 + 4]);
            *(float4*)(b2)     = *(const float4*)(&Ks[kk][tx * 8]);
            *(float4*)(b2 + 4) = *(const float4*)(&Ks[kk][tx * 8 + 4]);
#pragma unroll
            for (int i = 0; i < 8; ++i)
#pragma unroll
                for (int j = 0; j < 8; ++j)
                    acc[i][j] += a[i] * b2[j];
        }
        __syncthreads();
    }

    const float scale = 0.125f;
    float* srow = S + (size_t)bh * NN * NN;
#pragma unroll
    for (int i = 0; i < 8; ++i) {
        const int m = i0 + ty * 8 + i;
#pragma unroll
        for (int j = 0; j < 8; j += 4) {
            const int n = j0 + tx * 8 + j;
            float4 v = make_float4(acc[i][j] * scale, acc[i][j + 1] * scale,
                                   acc[i][j + 2] * scale, acc[i][j + 3] * scale);
            *(float4*)(srow + (size_t)m * NN + n) = v;
        }
    }
}

__global__ void __launch_bounds__(256) softmax_rows(
    float* __restrict__ S, const float* __restrict__ mask)
{
    const int r = blockIdx.x;
    const int i = r & (NN - 1);
    const int bh = r >> 10;
    const int b = bh >> 4;
    float* row = S + (size_t)r * NN;
    const float* mrow = mask + b * NN;
    const int tid = threadIdx.x;
    __shared__ float red[256];

    const float mi = mrow[i];
    const int j = tid << 2;
    const float4 rv = *(const float4*)(row + j);
    const float4 mv = *(const float4*)(mrow + j);

    float mx = -INFINITY;
    if (mv.x != 0.f) mx = fmaxf(mx, rv.x);
    if (mv.y != 0.f) mx = fmaxf(mx, rv.y);
    if (mv.z != 0.f) mx = fmaxf(mx, rv.z);
    if (mv.w != 0.f) mx = fmaxf(mx, rv.w);
    red[tid] = mx;
    __syncthreads();
#pragma unroll
    for (int s = 128; s > 0; s >>= 1) {
        if (tid < s) red[tid] = fmaxf(red[tid], red[tid + s]);
        __syncthreads();
    }
    mx = red[0];
    __syncthreads();

    float4 e;
    e.x = (mv.x != 0.f) ? __expf(rv.x - mx) : 0.f;
    e.y = (mv.y != 0.f) ? __expf(rv.y - mx) : 0.f;
    e.z = (mv.z != 0.f) ? __expf(rv.z - mx) : 0.f;
    e.w = (mv.w != 0.f) ? __expf(rv.w - mx) : 0.f;

    red[tid] = e.x + e.y + e.z + e.w;
    __syncthreads();
#pragma unroll
    for (int s = 128; s > 0; s >>= 1) {
        if (tid < s) red[tid] += red[tid + s];
        __syncthreads();
    }
    const float sum = red[0];

    const bool validrow = (mi != 0.f) && (mx != -INFINITY);
    const float inv = validrow ? 1.f / sum : 0.f;
    e.x *= inv; e.y *= inv; e.z *= inv; e.w *= inv;
    *(float4*)(row + j) = e;
}

__global__ void __launch_bounds__(256) pv_gemm(
    const float* __restrict__ S, const float* __restrict__ qkv,
    float* __restrict__ ao)
{
    __shared__ float Ps[16][128];
    __shared__ float Vs[16][64];
    const int tid = threadIdx.x;
    const int tx = tid & 15;
    const int ty = tid >> 4;
    const int bh = blockIdx.y;
    const int b = bh >> 4;
    const int h = bh & 15;
    const int i0 = blockIdx.x * 128;
    const float* pbase = S + (size_t)bh * NN * NN;
    const float* vbase = qkv + (size_t)b * NN * QKVC + 2 * INNERC + h * DHH;
    float* obase = ao + (size_t)b * NN * INNERC + h * DHH;

    const int arow = tid >> 2;
    const int ak = (tid & 3) << 2;
    const int vk = tid >> 4;
    const int vn = (tid & 15) << 2;

    float acc[8][4];
#pragma unroll
    for (int i = 0; i < 8; ++i)
#pragma unroll
        for (int j = 0; j < 4; ++j) acc[i][j] = 0.f;

    for (int j0 = 0; j0 < NN; j0 += 16) {
        float4 p0 = *(const float4*)(pbase + (size_t)(i0 + arow) * NN + j0 + ak);
        float4 p1 = *(const float4*)(pbase + (size_t)(i0 + arow + 64) * NN + j0 + ak);
        Ps[ak + 0][arow] = p0.x; Ps[ak + 1][arow] = p0.y;
        Ps[ak + 2][arow] = p0.z; Ps[ak + 3][arow] = p0.w;
        Ps[ak + 0][arow + 64] = p1.x; Ps[ak + 1][arow + 64] = p1.y;
        Ps[ak + 2][arow + 64] = p1.z; Ps[ak + 3][arow + 64] = p1.w;

        float4 v0 = *(const float4*)(vbase + (size_t)(j0 + vk) * QKVC + vn);
        *(float4*)(&Vs[vk][vn]) = v0;
        __syncthreads();

#pragma unroll
        for (int kk = 0; kk < 16; ++kk) {
            float a[8], bb[4];
            *(float4*)(a)     = *(const float4*)(&Ps[kk][ty * 8]);
            *(float4*)(a + 4) = *(const float4*)(&Ps[kk][ty * 8 + 4]);
            *(float4*)(bb)    = *(const float4*)(&Vs[kk][tx * 4]);
#pragma unroll
            for (int i = 0; i < 8; ++i)
#pragma unroll
                for (int j = 0; j < 4; ++j)
                    acc[i][j] += a[i] * bb[j];
        }
        __syncthreads();
    }

#pragma unroll
    for (int i = 0; i < 8; ++i) {
        const int m = i0 + ty * 8 + i;
        float4 v = make_float4(acc[i][0], acc[i][1], acc[i][2], acc[i][3]);
        *(float4*)(obase + (size_t)m * INNERC + tx * 4) = v;
    }
}

// ---------------------------------------------------------------------------
extern "C" void kernel_launch(void* const* d_in, const int* in_sizes, int n_in,
                              void* d_out, int out_size)
{
    const float* x      = (const float*)d_in[0];
    const float* mask   = (const float*)d_in[1];
    const float* w_qkv  = (const float*)d_in[2];
    const float* w_out  = (const float*)d_in[3];
    const float* b_out  = (const float*)d_in[4];
    float* out = (float*)d_out;

    float *qkv, *S, *ao;
    cudaGetSymbolAddress((void**)&qkv, g_qkv);
    cudaGetSymbolAddress((void**)&S, g_S);
    cudaGetSymbolAddress((void**)&ao, g_ao);
    __nv_bfloat16 *xhi, *xlo, *wqhi, *wqlo, *wohi, *wolo, *aohi, *aolo;
    cudaGetSymbolAddress((void**)&xhi, g_xhi);
    cudaGetSymbolAddress((void**)&xlo, g_xlo);
    cudaGetSymbolAddress((void**)&wqhi, g_wqkvThi);
    cudaGetSymbolAddress((void**)&wqlo, g_wqkvTlo);
    cudaGetSymbolAddress((void**)&wohi, g_woutThi);
    cudaGetSymbolAddress((void**)&wolo, g_woutTlo);
    cudaGetSymbolAddress((void**)&aohi, g_aohi);
    cudaGetSymbolAddress((void**)&aolo, g_aolo);

    cudaFuncSetAttribute(gemm_mma, cudaFuncAttributeMaxDynamicSharedMemorySize,
                         GEMM_SMEM_BYTES);

    // 0) bf16 hi/lo splits of GEMM operands
    split_kernel<<<(MM * DD / 4 + 255) / 256, 256>>>(x, xhi, xlo, MM * DD / 4);
    splitT_kernel<<<dim3(QKVC / 32, DD / 32), dim3(32, 8)>>>(w_qkv, wqhi, wqlo, DD, QKVC);
    splitT_kernel<<<dim3(INNERC / 32, INNERC / 32), dim3(32, 8)>>>(w_out, wohi, wolo,
                                                                   INNERC, INNERC);
    // 1) qkv = x @ w_qkv   (mma.sync bf16, 3-product)
    gemm_mma<<<dim3(QKVC / 128, MM / 128), 256, GEMM_SMEM_BYTES>>>(
        xhi, xlo, wqhi, wqlo, nullptr, qkv, MM, QKVC, DD);
    // 2) S = (1/8) q k^T per head
    qk_scores<<<dim3(NN / 128, NN / 128, BHC), 256>>>(qkv, S);
    // 3) masked softmax in place
    softmax_rows<<<BHC * NN, 256>>>(S, mask);
    // 4) ao = P @ V per head
    pv_gemm<<<dim3(NN / 128, BHC), 256>>>(S, qkv, ao);
    // 5) out = ao @ w_out + b_out   (mma.sync bf16)
    split_kernel<<<(MM * INNERC / 4 + 255) / 256, 256>>>(ao, aohi, aolo, MM * INNERC / 4);
    gemm_mma<<<dim3(INNERC / 128, MM / 128), 256, GEMM_SMEM_BYTES>>>(
        aohi, aolo, wohi, wolo, b_out, out, MM, INNERC, INNERC);
}